// round 7
// baseline (speedup 1.0000x reference)
#include <cuda_runtime.h>

#define NB   32768
#define PP   32
#define NCC  33
#define NBLK 512   // 2 sides x 256 item-blocks (128 items per block, 2 threads/item)
#define TPB  256

__device__ float g_partials[NBLK];
__device__ int   g_count;   // zero-init; reset by finishing block each launch

typedef unsigned long long ull;

__device__ __forceinline__ ull ffma2(ull a, ull b, ull c) {
    ull d; asm("fma.rn.f32x2 %0, %1, %2, %3;" : "=l"(d) : "l"(a), "l"(b), "l"(c)); return d;
}
__device__ __forceinline__ ull fadd2(ull a, ull b) {
    ull d; asm("add.rn.f32x2 %0, %1, %2;" : "=l"(d) : "l"(a), "l"(b)); return d;
}
__device__ __forceinline__ ull fmul2(ull a, ull b) {
    ull d; asm("mul.rn.f32x2 %0, %1, %2;" : "=l"(d) : "l"(a), "l"(b)); return d;
}
__device__ __forceinline__ ull pack2(float lo, float hi) {
    ull d; asm("mov.b64 %0, {%1, %2};" : "=l"(d) : "f"(lo), "f"(hi)); return d;
}
__device__ __forceinline__ float2 unpack2(ull v) {
    float2 r; asm("mov.b64 {%0, %1}, %2;" : "=f"(r.x), "=f"(r.y) : "l"(v)); return r;
}

// Cross-entropy from a shared-memory row (stride-33 => conflict-free; lane
// pairs read the same row -> broadcast, no penalty).
__device__ __forceinline__ float ce_smem(const float* __restrict__ row, int tgt, int* amax_out) {
    float m = -1e30f; int amax = 0;
#pragma unroll
    for (int j = 0; j < NCC; j++) {
        float x = row[j];
        if (x > m) { m = x; amax = j; }
    }
    float s = 0.f;
#pragma unroll
    for (int j = 0; j < NCC; j++)
        s += __expf(row[j] - m);
    *amax_out = amax;
    return m + __logf(s) - row[tgt];
}

// Two pred points (one float4) vs this thread's 8 packed target pairs, then
// complete the min over all 32 targets via a lane-pair shuffle (exact).
__device__ __forceinline__ void pair_body(float4 p, int i, int np,
                                          const ull* __restrict__ TX,
                                          const ull* __restrict__ TY,
                                          float* __restrict__ mintlo,
                                          float* __restrict__ minthi,
                                          float& sum_minp, float& sum_psq) {
    const bool va = (2 * i < np), vb = (2 * i + 1 < np);
    float ax = p.x, ay = p.y, bx = p.z, by = p.w;
    if (va) sum_psq += ax * ax + ay * ay; else { ax = -1e18f; ay = -1e18f; }
    if (vb) sum_psq += bx * bx + by * by; else { bx = -1e18f; by = -1e18f; }

    const ull AX = pack2(ax, ax), AY = pack2(ay, ay);
    const ull BX = pack2(bx, bx), BY = pack2(by, by);

    float mina = 1e30f, minb = 1e30f;
#pragma unroll
    for (int j = 0; j < PP / 4; j++) {
        ull dxa = fadd2(AX, TX[j]);
        ull dya = fadd2(AY, TY[j]);
        ull da  = ffma2(dxa, dxa, fmul2(dya, dya));
        ull dxb = fadd2(BX, TX[j]);
        ull dyb = fadd2(BY, TY[j]);
        ull db  = ffma2(dxb, dxb, fmul2(dyb, dyb));
        float2 daf = unpack2(da), dbf = unpack2(db);
        mina = fminf(mina, fminf(daf.x, daf.y));
        minb = fminf(minb, fminf(dbf.x, dbf.y));
        mintlo[j] = fminf(mintlo[j], fminf(daf.x, dbf.x));
        minthi[j] = fminf(minthi[j], fminf(daf.y, dbf.y));
    }
    // Partner thread holds the other 16 targets: combine (exact min).
    mina = fminf(mina, __shfl_xor_sync(0xFFFFFFFFu, mina, 1));
    minb = fminf(minb, __shfl_xor_sync(0xFFFFFFFFu, minb, 1));
    if (va) sum_minp += mina;
    if (vb) sum_minp += minb;
}

// Chamfer split across a lane pair: this thread owns targets
// [half*16, half*16+16) resident in registers, streams all 32 pred points.
// Both threads of the pair return the identical per-item chamfer value.
__device__ __forceinline__ float chamfer_split(const float4* __restrict__ pred4,
                                               const float4* __restrict__ tgt4,
                                               int np, int nt, int half) {
    ull TX[PP / 4], TY[PP / 4];
    float sum_tsq_loc = 0.f;
#pragma unroll
    for (int j = 0; j < PP / 4; j++) {
        float4 t = __ldg(tgt4 + half * (PP / 4) + j);
        const int g = half * (PP / 2) + 2 * j;
        float x0, y0, x1, y1;
        if (g < nt)     { sum_tsq_loc += t.x * t.x + t.y * t.y; x0 = -t.x; y0 = -t.y; }
        else            { x0 = -1e18f; y0 = -1e18f; }
        if (g + 1 < nt) { sum_tsq_loc += t.z * t.z + t.w * t.w; x1 = -t.z; y1 = -t.w; }
        else            { x1 = -1e18f; y1 = -1e18f; }
        TX[j] = pack2(x0, x1); TY[j] = pack2(y0, y1);
    }

    float mintlo[PP / 4], minthi[PP / 4];
#pragma unroll
    for (int j = 0; j < PP / 4; j++) { mintlo[j] = 1e30f; minthi[j] = 1e30f; }

    float sum_minp = 0.f, sum_psq = 0.f;

    // Stream preds: chunk = 2 float4 with one-chunk lookahead.
    float4 c0 = __ldg(pred4 + 0);
    float4 c1 = __ldg(pred4 + 1);
#pragma unroll 1
    for (int c = 0; c < 8; c++) {
        float4 n0, n1;
        if (c < 7) {
            n0 = __ldg(pred4 + 2 * c + 2);
            n1 = __ldg(pred4 + 2 * c + 3);
        }
        pair_body(c0, 2 * c + 0, np, TX, TY, mintlo, minthi, sum_minp, sum_psq);
        pair_body(c1, 2 * c + 1, np, TX, TY, mintlo, minthi, sum_minp, sum_psq);
        c0 = n0; c1 = n1;
    }

    float sum_mint_loc = 0.f;
#pragma unroll
    for (int j = 0; j < PP / 4; j++) {
        const int g = half * (PP / 2) + 2 * j;
        if (g < nt)     sum_mint_loc += mintlo[j];
        if (g + 1 < nt) sum_mint_loc += minthi[j];
    }
    // Combine halves (commutative adds -> identical on both threads).
    const float sum_mint = sum_mint_loc + __shfl_xor_sync(0xFFFFFFFFu, sum_mint_loc, 1);
    const float sum_tsq  = sum_tsq_loc  + __shfl_xor_sync(0xFFFFFFFFu, sum_tsq_loc, 1);

    if (np == 0 && nt == 0) return 0.f;
    if (np == 0) return sum_tsq;
    if (nt == 0) return sum_psq;
    return sum_minp / (float)np + sum_mint / (float)nt;
}

// Block = 256 threads = 128 items on ONE side; lane pair (2k, 2k+1) -> item k.
//   side = blockIdx.x & 1, item-block = blockIdx.x >> 1.
__global__ __launch_bounds__(TPB, 2)
void loss_kernel(const float*  __restrict__ pole_logits,
                 const float*  __restrict__ zero_logits,
                 const float4* __restrict__ poles,
                 const float4* __restrict__ zeros,
                 const float4* __restrict__ tpoles,
                 const float4* __restrict__ tzeros,
                 const int*    __restrict__ tnp,
                 const int*    __restrict__ tnz,
                 float*        __restrict__ out) {
    __shared__ __align__(16) float slog[128 * NCC];   // 16896 B
    __shared__ float sred[TPB];
    __shared__ int   sflag;

    const int tid  = threadIdx.x;
    const int side = blockIdx.x & 1;
    const int ib   = blockIdx.x >> 1;
    const int item = tid >> 1;
    const int half = tid & 1;
    const int b    = ib * 128 + item;

    const float*  logits = side ? zero_logits : pole_logits;
    const float4* pred   = side ? zeros       : poles;
    const float4* tgt    = side ? tzeros      : tpoles;
    const int*    tn     = side ? tnz         : tnp;

    // Coalesced float4 staging of 128 logit rows (1056 float4) by 256 threads.
    {
        const float4* src = (const float4*)(logits + (size_t)ib * 128 * NCC);
        float4* dst = (float4*)slog;
#pragma unroll
        for (int k = 0; k < 4; k++)
            dst[tid + TPB * k] = __ldg(src + tid + TPB * k);
        if (tid < 32)
            dst[1024 + tid] = __ldg(src + 1024 + tid);
    }
    if (tid == 0) sflag = 0;
    __syncthreads();

    const int tc = __ldg(tn + b);
    int pred_n;
    const float ce = ce_smem(&slog[item * NCC], tc, &pred_n);  // both lanes: identical
    const float ch = chamfer_split(pred + (size_t)b * (PP / 2),
                                   tgt  + (size_t)b * (PP / 2), pred_n, tc, half);
    float acc = half ? 0.f : (5.f * ce + ch);   // count each item once

    // Deterministic block tree reduction (256 threads)
    sred[tid] = acc;
    __syncthreads();
#pragma unroll
    for (int s = TPB / 2; s > 0; s >>= 1) {
        if (tid < s) sred[tid] += sred[tid + s];
        __syncthreads();
    }

    if (tid == 0) {
        g_partials[blockIdx.x] = sred[0];
        __threadfence();
        unsigned n = atomicAdd(&g_count, 1);
        if (n == NBLK - 1) sflag = 1;
    }
    __syncthreads();

    // Last block: deterministic fixed-order tree over all 512 partials.
    if (sflag) {
        __threadfence();
        volatile float* vp = g_partials;
        sred[tid] = vp[tid] + vp[tid + TPB];
        __syncthreads();
#pragma unroll
        for (int s = TPB / 2; s > 0; s >>= 1) {
            if (tid < s) sred[tid] += sred[tid + s];
            __syncthreads();
        }
        if (tid == 0) {
            out[0] = sred[0] * (1.0f / (float)NB);
            g_count = 0;   // reset for next graph replay
        }
    }
}

extern "C" void kernel_launch(void* const* d_in, const int* in_sizes, int n_in,
                              void* d_out, int out_size) {
    const float*  pole_logits = (const float*)d_in[0];
    const float*  zero_logits = (const float*)d_in[1];
    const float4* poles       = (const float4*)d_in[2];
    const float4* zeros       = (const float4*)d_in[3];
    const float4* tpoles      = (const float4*)d_in[4];
    const float4* tzeros      = (const float4*)d_in[5];
    const int*    tnp         = (const int*)d_in[6];
    const int*    tnz         = (const int*)d_in[7];

    loss_kernel<<<NBLK, TPB>>>(pole_logits, zero_logits, poles, zeros,
                               tpoles, tzeros, tnp, tnz, (float*)d_out);
}